// round 1
// baseline (speedup 1.0000x reference)
#include <cuda_runtime.h>
#include <math.h>

// Problem constants (fixed by dataset)
#define NN_ 8192      // nodes
#define FF_ 512       // input features
#define HH_ 256       // hidden
#define RR_ 16        // relations
#define BB_ 32        // batch (conversations)
#define LL_ 256       // seq length
#define CC_ 7         // classes
#define EE_ 262144    // edges
#define NBASE_ 30     // bases
#define DD_ 768       // F + H
#define RH_ 4096      // R * H

// ---------------- scratch (static device globals; no allocation) ----------------
__device__ __align__(16) float g_W[FF_ * RH_];                 // 8 MB
__device__ __align__(16) float g_xw[(size_t)NN_ * RH_];        // 134 MB
__device__ int                 g_cnt[NN_ * RR_];
__device__ __align__(16) float g_out1[NN_ * HH_];
__device__ __align__(16) float g_agg2[NN_ * HH_];
__device__ __align__(16) float g_emo[NN_ * DD_];
__device__ __align__(16) float g_X[NN_ * DD_];
__device__ __align__(16) float g_scores[BB_ * LL_ * LL_];
__device__ __align__(16) float g_att[NN_ * DD_];
__device__ __align__(16) float g_hidden[NN_ * HH_];
__device__ __align__(16) float g_logits[NN_ * CC_];

// ---------------- generic tiled FP32 GEMM: C = A @ B (or A @ B^T) ----------------
// 128x128 tile, BK=8, 256 threads, 8x8 per thread.
// EPI: 0=none 1=relu 2=tanh.  ACC: C += result.  BIAS: add bias[n].
template <int TRANSB, int EPI, int ACC, int BIAS>
__global__ void __launch_bounds__(256, 2) gemm_k(
    const float* __restrict__ A, const float* __restrict__ B,
    float* __restrict__ C, const float* __restrict__ bias,
    int M, int N, int K, int lda, int ldb, int ldc,
    long long sA, long long sB, long long sC)
{
    __shared__ float As[8][128];
    __shared__ float Bs[8][128];
    A += (long long)blockIdx.z * sA;
    B += (long long)blockIdx.z * sB;
    C += (long long)blockIdx.z * sC;
    const int bm = blockIdx.y * 128;
    const int bn = blockIdx.x * 128;
    const int tid = threadIdx.x;
    const int tx = tid & 15, ty = tid >> 4;

    float acc[8][8];
#pragma unroll
    for (int i = 0; i < 8; i++)
#pragma unroll
        for (int j = 0; j < 8; j++) acc[i][j] = 0.f;

    const int am = tid >> 1, ak = (tid & 1) * 4;   // A: one float4/thread

    for (int k0 = 0; k0 < K; k0 += 8) {
        {   // A tile (transposed into smem)
            float4 v = make_float4(0.f, 0.f, 0.f, 0.f);
            int gm = bm + am;
            if (gm < M) v = *(const float4*)(A + (long long)gm * lda + k0 + ak);
            As[ak + 0][am] = v.x; As[ak + 1][am] = v.y;
            As[ak + 2][am] = v.z; As[ak + 3][am] = v.w;
        }
        if (TRANSB == 0) {
            int bk = tid >> 5, cn = (tid & 31) * 4;
            float4 v = make_float4(0.f, 0.f, 0.f, 0.f);
            if (bn + cn < N) v = *(const float4*)(B + (long long)(k0 + bk) * ldb + bn + cn);
            *(float4*)&Bs[bk][cn] = v;
        } else {
            int nn = tid >> 1, kq = (tid & 1) * 4;
            float4 v = make_float4(0.f, 0.f, 0.f, 0.f);
            if (bn + nn < N) v = *(const float4*)(B + (long long)(bn + nn) * ldb + k0 + kq);
            Bs[kq + 0][nn] = v.x; Bs[kq + 1][nn] = v.y;
            Bs[kq + 2][nn] = v.z; Bs[kq + 3][nn] = v.w;
        }
        __syncthreads();
#pragma unroll
        for (int kk = 0; kk < 8; ++kk) {
            float ra[8], rb[8];
            *(float4*)&ra[0] = *(const float4*)&As[kk][ty * 8];
            *(float4*)&ra[4] = *(const float4*)&As[kk][ty * 8 + 4];
            *(float4*)&rb[0] = *(const float4*)&Bs[kk][tx * 8];
            *(float4*)&rb[4] = *(const float4*)&Bs[kk][tx * 8 + 4];
#pragma unroll
            for (int i = 0; i < 8; i++)
#pragma unroll
                for (int j = 0; j < 8; j++)
                    acc[i][j] = fmaf(ra[i], rb[j], acc[i][j]);
        }
        __syncthreads();
    }
#pragma unroll
    for (int i = 0; i < 8; i++) {
        int m = bm + ty * 8 + i;
        if (m >= M) continue;
#pragma unroll
        for (int j = 0; j < 8; j++) {
            int n = bn + tx * 8 + j;
            if (n >= N) continue;
            float v = acc[i][j];
            if (BIAS) v += bias[n];
            if (ACC)  v += C[(long long)m * ldc + n];
            if (EPI == 1) v = fmaxf(v, 0.f);
            if (EPI == 2) v = tanhf(v);
            C[(long long)m * ldc + n] = v;
        }
    }
}

// ---------------- small kernels ----------------
__global__ void zero_f_k(float* p, int n) {
    int i = blockIdx.x * 256 + threadIdx.x;
    if (i < n) p[i] = 0.f;
}

// W[r,f,h] = sum_b comp[r,b] * basis[b,f,h], stored as Wcat[f, r*256+h]
__global__ void computeW_k(const float* __restrict__ basis, const float* __restrict__ comp) {
    int i = blockIdx.x * 256 + threadIdx.x;        // over F*RH
    if (i >= FF_ * RH_) return;
    int h = i & 255;
    int r = (i >> 8) & 15;
    int f = i >> 12;
    float s = 0.f;
#pragma unroll
    for (int b = 0; b < NBASE_; b++)
        s = fmaf(comp[r * NBASE_ + b], basis[((size_t)b * FF_ + f) * HH_ + h], s);
    g_W[(size_t)f * RH_ + r * HH_ + h] = s;
}

__global__ void count_k(const int* __restrict__ ei, const int* __restrict__ et) {
    int e = blockIdx.x * 256 + threadIdx.x;
    if (e < EE_) atomicAdd(&g_cnt[ei[EE_ + e] * RR_ + et[e]], 1);
}

// out1[dst] += xw[src, etype] / cnt[dst, etype]   (one warp per edge)
__global__ void scatter_msg_k(const int* __restrict__ ei, const int* __restrict__ et) {
    int e = blockIdx.x * 8 + (threadIdx.x >> 5);
    int lane = threadIdx.x & 31;
    if (e >= EE_) return;
    int s = ei[e], d = ei[EE_ + e], r = et[e];
    float inv = 1.0f / (float)max(g_cnt[d * RR_ + r], 1);
    const float4* p = (const float4*)(g_xw + (size_t)s * RH_ + r * HH_);
    float* o = g_out1 + (size_t)d * HH_;
#pragma unroll
    for (int i = 0; i < 2; ++i) {
        float4 v = p[lane + i * 32];
        int h = (lane + i * 32) * 4;
        atomicAdd(o + h + 0, v.x * inv);
        atomicAdd(o + h + 1, v.y * inv);
        atomicAdd(o + h + 2, v.z * inv);
        atomicAdd(o + h + 3, v.w * inv);
    }
}

// agg2[dst] += out1[src]
__global__ void scatter_agg2_k(const int* __restrict__ ei) {
    int e = blockIdx.x * 8 + (threadIdx.x >> 5);
    int lane = threadIdx.x & 31;
    if (e >= EE_) return;
    int s = ei[e], d = ei[EE_ + e];
    const float4* p = (const float4*)(g_out1 + (size_t)s * HH_);
    float* o = g_agg2 + (size_t)d * HH_;
#pragma unroll
    for (int i = 0; i < 2; ++i) {
        float4 v = p[lane + i * 32];
        int h = (lane + i * 32) * 4;
        atomicAdd(o + h + 0, v.x);
        atomicAdd(o + h + 1, v.y);
        atomicAdd(o + h + 2, v.z);
        atomicAdd(o + h + 3, v.w);
    }
}

// emotions[:, 0:512] = x
__global__ void copyx_k(const float* __restrict__ x) {
    int i = blockIdx.x * 256 + threadIdx.x;        // over N*F/4 float4s
    if (i >= NN_ * FF_ / 4) return;
    int n = i >> 7;           // / 128
    int f4 = i & 127;
    ((float4*)(g_emo + (size_t)n * DD_))[f4] = ((const float4*)x)[i];
}

// row-wise softmax over last dim (256) of g_scores; one block per row
__global__ void softmax_k() {
    float* row = g_scores + (size_t)blockIdx.x * LL_;
    int t = threadIdx.x;
    int lane = t & 31, w = t >> 5;
    __shared__ float red[8];
    float v = row[t];
    float m = v;
#pragma unroll
    for (int o = 16; o > 0; o >>= 1) m = fmaxf(m, __shfl_xor_sync(0xffffffffu, m, o));
    if (lane == 0) red[w] = m;
    __syncthreads();
    m = red[0];
#pragma unroll
    for (int i = 1; i < 8; i++) m = fmaxf(m, red[i]);
    float e = expf(v - m);
    float s = e;
#pragma unroll
    for (int o = 16; o > 0; o >>= 1) s += __shfl_xor_sync(0xffffffffu, s, o);
    __syncthreads();
    if (lane == 0) red[w] = s;
    __syncthreads();
    s = 0.f;
#pragma unroll
    for (int i = 0; i < 8; i++) s += red[i];
    row[t] = e / s;
}

// logits[n,c] = hidden[n,:] . w_fc[:,c] + b_fc[c]   (one warp per node)
__global__ void logits_k(const float* __restrict__ wfc, const float* __restrict__ bfc) {
    __shared__ float sw[HH_ * CC_];
    for (int i = threadIdx.x; i < HH_ * CC_; i += 256) sw[i] = wfc[i];
    __syncthreads();
    int n = blockIdx.x * 8 + (threadIdx.x >> 5);
    int lane = threadIdx.x & 31;
    const float* h = g_hidden + (size_t)n * HH_;
    float a[CC_];
#pragma unroll
    for (int c = 0; c < CC_; c++) a[c] = 0.f;
    for (int k = lane; k < HH_; k += 32) {
        float hv = h[k];
#pragma unroll
        for (int c = 0; c < CC_; c++) a[c] = fmaf(hv, sw[k * CC_ + c], a[c]);
    }
#pragma unroll
    for (int c = 0; c < CC_; c++)
#pragma unroll
        for (int o = 16; o > 0; o >>= 1) a[c] += __shfl_xor_sync(0xffffffffu, a[c], o);
    if (lane == 0) {
#pragma unroll
        for (int c = 0; c < CC_; c++) g_logits[(size_t)n * CC_ + c] = a[c] + bfc[c];
    }
}

// out[t,b,c] = logits[(b*L+t), c] - logsumexp over b (axis=1 of [L,B,C])
__global__ void logsoftmax_k(float* __restrict__ out) {
    int u = blockIdx.x * 256 + threadIdx.x;
    if (u >= LL_ * CC_) return;
    int t = u / CC_, c = u % CC_;
    float vals[BB_];
    float m = -1e30f;
#pragma unroll
    for (int b = 0; b < BB_; b++) {
        vals[b] = g_logits[((size_t)(b * LL_ + t)) * CC_ + c];
        m = fmaxf(m, vals[b]);
    }
    float s = 0.f;
#pragma unroll
    for (int b = 0; b < BB_; b++) s += expf(vals[b] - m);
    float lse = m + logf(s);
#pragma unroll
    for (int b = 0; b < BB_; b++) out[((size_t)t * BB_ + b) * CC_ + c] = vals[b] - lse;
}

// ---------------- host launcher ----------------
static inline dim3 ggrid(int M, int N, int batch) {
    return dim3((N + 127) / 128, (M + 127) / 128, batch);
}

extern "C" void kernel_launch(void* const* d_in, const int* in_sizes, int n_in,
                              void* d_out, int out_size)
{
    const float* x      = (const float*)d_in[0];
    const int*   ei     = (const int*)  d_in[1];
    const int*   et     = (const int*)  d_in[3];
    const float* basis  = (const float*)d_in[8];
    const float* comp   = (const float*)d_in[9];
    const float* root1  = (const float*)d_in[10];
    const float* bias1  = (const float*)d_in[11];
    const float* w_rel  = (const float*)d_in[12];
    const float* b_rel  = (const float*)d_in[13];
    const float* w_root = (const float*)d_in[14];
    const float* w_att  = (const float*)d_in[15];
    const float* b_att  = (const float*)d_in[16];
    const float* w_lin  = (const float*)d_in[17];
    const float* b_lin  = (const float*)d_in[18];
    const float* w_fc   = (const float*)d_in[19];
    const float* b_fc   = (const float*)d_in[20];
    float* out = (float*)d_out;

    float *pW, *pxw, *pout1, *pagg2, *pemo, *pX, *pscores, *patt, *phid;
    int* pcnt;
    cudaGetSymbolAddress((void**)&pW,      g_W);
    cudaGetSymbolAddress((void**)&pxw,     g_xw);
    cudaGetSymbolAddress((void**)&pcnt,    g_cnt);
    cudaGetSymbolAddress((void**)&pout1,   g_out1);
    cudaGetSymbolAddress((void**)&pagg2,   g_agg2);
    cudaGetSymbolAddress((void**)&pemo,    g_emo);
    cudaGetSymbolAddress((void**)&pX,      g_X);
    cudaGetSymbolAddress((void**)&pscores, g_scores);
    cudaGetSymbolAddress((void**)&patt,    g_att);
    cudaGetSymbolAddress((void**)&phid,    g_hidden);

    // 1) zero counters & agg2
    zero_f_k<<<(NN_ * RR_ + 255) / 256, 256>>>((float*)pcnt, NN_ * RR_);
    zero_f_k<<<(NN_ * HH_ + 255) / 256, 256>>>(pagg2, NN_ * HH_);

    // 2) edge counts per (dst, rel)
    count_k<<<EE_ / 256, 256>>>(ei, et);

    // 3) W = comp x basis  -> Wcat[F, R*H]
    computeW_k<<<(FF_ * RH_ + 255) / 256, 256>>>(basis, comp);

    // 4) xw = x @ Wcat   [N, RH]
    gemm_k<0, 0, 0, 0><<<ggrid(NN_, RH_, 1), 256>>>(
        x, pW, pxw, nullptr, NN_, RH_, FF_, FF_, RH_, RH_, 0, 0, 0);

    // 5) out1 = x @ root1 + bias1
    gemm_k<0, 0, 0, 1><<<ggrid(NN_, HH_, 1), 256>>>(
        x, root1, pout1, bias1, NN_, HH_, FF_, FF_, HH_, HH_, 0, 0, 0);

    // 6) out1 += scatter(mean per (dst,rel) of xw[src,etype])
    scatter_msg_k<<<EE_ / 8, 256>>>(ei, et);

    // 7) agg2 = scatter_sum(out1[src] -> dst)
    scatter_agg2_k<<<EE_ / 8, 256>>>(ei);

    // 8) emotions = [x | agg2@w_rel + b_rel + out1@w_root]
    copyx_k<<<(NN_ * FF_ / 4 + 255) / 256, 256>>>(x);
    gemm_k<0, 0, 0, 1><<<ggrid(NN_, HH_, 1), 256>>>(
        pagg2, w_rel, pemo + FF_, b_rel, NN_, HH_, HH_, HH_, HH_, DD_, 0, 0, 0);
    gemm_k<0, 0, 1, 0><<<ggrid(NN_, HH_, 1), 256>>>(
        pout1, w_root, pemo + FF_, nullptr, NN_, HH_, HH_, HH_, HH_, DD_, 0, 0, 0);

    // 9) X = emotions @ w_att + b_att
    gemm_k<0, 0, 0, 1><<<ggrid(NN_, DD_, 1), 256>>>(
        pemo, w_att, pX, b_att, NN_, DD_, DD_, DD_, DD_, DD_, 0, 0, 0);

    // 10) scores[b] = tanh(X_b @ M_b^T)   (batched NT, epilogue tanh)
    gemm_k<1, 2, 0, 0><<<ggrid(LL_, LL_, BB_), 256>>>(
        pX, pemo, pscores, nullptr, LL_, LL_, DD_, DD_, DD_, LL_,
        (long long)LL_ * DD_, (long long)LL_ * DD_, (long long)LL_ * LL_);

    // 11) row softmax over s
    softmax_k<<<BB_ * LL_, LL_>>>();

    // 12) att[b] = a_b @ M_b   (batched NN)
    gemm_k<0, 0, 0, 0><<<ggrid(LL_, DD_, BB_), 256>>>(
        pscores, pemo, patt, nullptr, LL_, DD_, LL_, LL_, DD_, DD_,
        (long long)LL_ * LL_, (long long)LL_ * DD_, (long long)LL_ * DD_);

    // 13) hidden = relu(att @ w_lin + b_lin)
    gemm_k<0, 1, 0, 1><<<ggrid(NN_, HH_, 1), 256>>>(
        patt, w_lin, phid, b_lin, NN_, HH_, DD_, DD_, HH_, HH_, 0, 0, 0);

    // 14) logits = hidden @ w_fc + b_fc
    logits_k<<<NN_ / 8, 256>>>(w_fc, b_fc);

    // 15) log_softmax over batch axis, write [L,B,C]
    logsoftmax_k<<<(LL_ * CC_ + 255) / 256, 256>>>(out);
}

// round 2
// speedup vs baseline: 1.0002x; 1.0002x over previous
#include <cuda_runtime.h>
#include <math.h>

// Problem constants (fixed by dataset)
#define NN_ 8192      // nodes
#define FF_ 512       // input features
#define HH_ 256       // hidden
#define RR_ 16        // relations
#define BB_ 32        // batch (conversations)
#define LL_ 256       // seq length
#define CC_ 7         // classes
#define EE_ 262144    // edges
#define NBASE_ 30     // bases
#define DD_ 768       // F + H
#define RH_ 4096      // R * H

// ---------------- scratch (static device globals; no allocation) ----------------
__device__ __align__(16) float g_W[FF_ * RH_];                 // 8 MB
__device__ __align__(16) float g_xw[(size_t)NN_ * RH_];        // 134 MB
__device__ int                 g_cnt[NN_ * RR_];
__device__ __align__(16) float g_out1[NN_ * HH_];
__device__ __align__(16) float g_agg2[NN_ * HH_];
__device__ __align__(16) float g_emo[NN_ * DD_];
__device__ __align__(16) float g_X[NN_ * DD_];
__device__ __align__(16) float g_scores[BB_ * LL_ * LL_];
__device__ __align__(16) float g_att[NN_ * DD_];
__device__ __align__(16) float g_hidden[NN_ * HH_];
__device__ __align__(16) float g_logits[NN_ * CC_];

// ---------------- generic tiled FP32 GEMM: C = A @ B (or A @ B^T) ----------------
// 128x128 tile, BK=8, 256 threads, 8x8 per thread.
// EPI: 0=none 1=relu 2=tanh.  ACC: C += result.  BIAS: add bias[n].
template <int TRANSB, int EPI, int ACC, int BIAS>
__global__ void __launch_bounds__(256, 2) gemm_k(
    const float* __restrict__ A, const float* __restrict__ B,
    float* __restrict__ C, const float* __restrict__ bias,
    int M, int N, int K, int lda, int ldb, int ldc,
    long long sA, long long sB, long long sC)
{
    __shared__ float As[8][128];
    __shared__ float Bs[8][128];
    A += (long long)blockIdx.z * sA;
    B += (long long)blockIdx.z * sB;
    C += (long long)blockIdx.z * sC;
    const int bm = blockIdx.y * 128;
    const int bn = blockIdx.x * 128;
    const int tid = threadIdx.x;
    const int tx = tid & 15, ty = tid >> 4;

    float acc[8][8];
#pragma unroll
    for (int i = 0; i < 8; i++)
#pragma unroll
        for (int j = 0; j < 8; j++) acc[i][j] = 0.f;

    const int am = tid >> 1, ak = (tid & 1) * 4;   // A: one float4/thread

    for (int k0 = 0; k0 < K; k0 += 8) {
        {   // A tile (transposed into smem)
            float4 v = make_float4(0.f, 0.f, 0.f, 0.f);
            int gm = bm + am;
            if (gm < M) v = *(const float4*)(A + (long long)gm * lda + k0 + ak);
            As[ak + 0][am] = v.x; As[ak + 1][am] = v.y;
            As[ak + 2][am] = v.z; As[ak + 3][am] = v.w;
        }
        if (TRANSB == 0) {
            int bk = tid >> 5, cn = (tid & 31) * 4;
            float4 v = make_float4(0.f, 0.f, 0.f, 0.f);
            if (bn + cn < N) v = *(const float4*)(B + (long long)(k0 + bk) * ldb + bn + cn);
            *(float4*)&Bs[bk][cn] = v;
        } else {
            int nn = tid >> 1, kq = (tid & 1) * 4;
            float4 v = make_float4(0.f, 0.f, 0.f, 0.f);
            if (bn + nn < N) v = *(const float4*)(B + (long long)(bn + nn) * ldb + k0 + kq);
            Bs[kq + 0][nn] = v.x; Bs[kq + 1][nn] = v.y;
            Bs[kq + 2][nn] = v.z; Bs[kq + 3][nn] = v.w;
        }
        __syncthreads();
#pragma unroll
        for (int kk = 0; kk < 8; ++kk) {
            float ra[8], rb[8];
            *(float4*)&ra[0] = *(const float4*)&As[kk][ty * 8];
            *(float4*)&ra[4] = *(const float4*)&As[kk][ty * 8 + 4];
            *(float4*)&rb[0] = *(const float4*)&Bs[kk][tx * 8];
            *(float4*)&rb[4] = *(const float4*)&Bs[kk][tx * 8 + 4];
#pragma unroll
            for (int i = 0; i < 8; i++)
#pragma unroll
                for (int j = 0; j < 8; j++)
                    acc[i][j] = fmaf(ra[i], rb[j], acc[i][j]);
        }
        __syncthreads();
    }
#pragma unroll
    for (int i = 0; i < 8; i++) {
        int m = bm + ty * 8 + i;
        if (m >= M) continue;
#pragma unroll
        for (int j = 0; j < 8; j++) {
            int n = bn + tx * 8 + j;
            if (n >= N) continue;
            float v = acc[i][j];
            if (BIAS) v += bias[n];
            if (ACC)  v += C[(long long)m * ldc + n];
            if (EPI == 1) v = fmaxf(v, 0.f);
            if (EPI == 2) v = tanhf(v);
            C[(long long)m * ldc + n] = v;
        }
    }
}

// ---------------- small kernels ----------------
__global__ void zero_f_k(float* p, int n) {
    int i = blockIdx.x * 256 + threadIdx.x;
    if (i < n) p[i] = 0.f;
}

// W[r,f,h] = sum_b comp[r,b] * basis[b,f,h], stored as Wcat[f, r*256+h]
__global__ void computeW_k(const float* __restrict__ basis, const float* __restrict__ comp) {
    int i = blockIdx.x * 256 + threadIdx.x;        // over F*RH
    if (i >= FF_ * RH_) return;
    int h = i & 255;
    int r = (i >> 8) & 15;
    int f = i >> 12;
    float s = 0.f;
#pragma unroll
    for (int b = 0; b < NBASE_; b++)
        s = fmaf(comp[r * NBASE_ + b], basis[((size_t)b * FF_ + f) * HH_ + h], s);
    g_W[(size_t)f * RH_ + r * HH_ + h] = s;
}

__global__ void count_k(const int* __restrict__ ei, const int* __restrict__ et) {
    int e = blockIdx.x * 256 + threadIdx.x;
    if (e < EE_) atomicAdd(&g_cnt[ei[EE_ + e] * RR_ + et[e]], 1);
}

// out1[dst] += xw[src, etype] / cnt[dst, etype]   (one warp per edge)
__global__ void scatter_msg_k(const int* __restrict__ ei, const int* __restrict__ et) {
    int e = blockIdx.x * 8 + (threadIdx.x >> 5);
    int lane = threadIdx.x & 31;
    if (e >= EE_) return;
    int s = ei[e], d = ei[EE_ + e], r = et[e];
    float inv = 1.0f / (float)max(g_cnt[d * RR_ + r], 1);
    const float4* p = (const float4*)(g_xw + (size_t)s * RH_ + r * HH_);
    float* o = g_out1 + (size_t)d * HH_;
#pragma unroll
    for (int i = 0; i < 2; ++i) {
        float4 v = p[lane + i * 32];
        int h = (lane + i * 32) * 4;
        atomicAdd(o + h + 0, v.x * inv);
        atomicAdd(o + h + 1, v.y * inv);
        atomicAdd(o + h + 2, v.z * inv);
        atomicAdd(o + h + 3, v.w * inv);
    }
}

// agg2[dst] += out1[src]
__global__ void scatter_agg2_k(const int* __restrict__ ei) {
    int e = blockIdx.x * 8 + (threadIdx.x >> 5);
    int lane = threadIdx.x & 31;
    if (e >= EE_) return;
    int s = ei[e], d = ei[EE_ + e];
    const float4* p = (const float4*)(g_out1 + (size_t)s * HH_);
    float* o = g_agg2 + (size_t)d * HH_;
#pragma unroll
    for (int i = 0; i < 2; ++i) {
        float4 v = p[lane + i * 32];
        int h = (lane + i * 32) * 4;
        atomicAdd(o + h + 0, v.x);
        atomicAdd(o + h + 1, v.y);
        atomicAdd(o + h + 2, v.z);
        atomicAdd(o + h + 3, v.w);
    }
}

// emotions[:, 0:512] = x
__global__ void copyx_k(const float* __restrict__ x) {
    int i = blockIdx.x * 256 + threadIdx.x;        // over N*F/4 float4s
    if (i >= NN_ * FF_ / 4) return;
    int n = i >> 7;           // / 128
    int f4 = i & 127;
    ((float4*)(g_emo + (size_t)n * DD_))[f4] = ((const float4*)x)[i];
}

// row-wise softmax over last dim (256) of g_scores; one block per row
__global__ void softmax_k() {
    float* row = g_scores + (size_t)blockIdx.x * LL_;
    int t = threadIdx.x;
    int lane = t & 31, w = t >> 5;
    __shared__ float red[8];
    float v = row[t];
    float m = v;
#pragma unroll
    for (int o = 16; o > 0; o >>= 1) m = fmaxf(m, __shfl_xor_sync(0xffffffffu, m, o));
    if (lane == 0) red[w] = m;
    __syncthreads();
    m = red[0];
#pragma unroll
    for (int i = 1; i < 8; i++) m = fmaxf(m, red[i]);
    float e = expf(v - m);
    float s = e;
#pragma unroll
    for (int o = 16; o > 0; o >>= 1) s += __shfl_xor_sync(0xffffffffu, s, o);
    __syncthreads();
    if (lane == 0) red[w] = s;
    __syncthreads();
    s = 0.f;
#pragma unroll
    for (int i = 0; i < 8; i++) s += red[i];
    row[t] = e / s;
}

// logits[n,c] = hidden[n,:] . w_fc[:,c] + b_fc[c]   (one warp per node)
__global__ void logits_k(const float* __restrict__ wfc, const float* __restrict__ bfc) {
    __shared__ float sw[HH_ * CC_];
    for (int i = threadIdx.x; i < HH_ * CC_; i += 256) sw[i] = wfc[i];
    __syncthreads();
    int n = blockIdx.x * 8 + (threadIdx.x >> 5);
    int lane = threadIdx.x & 31;
    const float* h = g_hidden + (size_t)n * HH_;
    float a[CC_];
#pragma unroll
    for (int c = 0; c < CC_; c++) a[c] = 0.f;
    for (int k = lane; k < HH_; k += 32) {
        float hv = h[k];
#pragma unroll
        for (int c = 0; c < CC_; c++) a[c] = fmaf(hv, sw[k * CC_ + c], a[c]);
    }
#pragma unroll
    for (int c = 0; c < CC_; c++)
#pragma unroll
        for (int o = 16; o > 0; o >>= 1) a[c] += __shfl_xor_sync(0xffffffffu, a[c], o);
    if (lane == 0) {
#pragma unroll
        for (int c = 0; c < CC_; c++) g_logits[(size_t)n * CC_ + c] = a[c] + bfc[c];
    }
}

// out[t,b,c] = logits[(b*L+t), c] - logsumexp over b (axis=1 of [L,B,C])
__global__ void logsoftmax_k(float* __restrict__ out) {
    int u = blockIdx.x * 256 + threadIdx.x;
    if (u >= LL_ * CC_) return;
    int t = u / CC_, c = u % CC_;
    float vals[BB_];
    float m = -1e30f;
#pragma unroll
    for (int b = 0; b < BB_; b++) {
        vals[b] = g_logits[((size_t)(b * LL_ + t)) * CC_ + c];
        m = fmaxf(m, vals[b]);
    }
    float s = 0.f;
#pragma unroll
    for (int b = 0; b < BB_; b++) s += expf(vals[b] - m);
    float lse = m + logf(s);
#pragma unroll
    for (int b = 0; b < BB_; b++) out[((size_t)t * BB_ + b) * CC_ + c] = vals[b] - lse;
}

// ---------------- host launcher ----------------
static inline dim3 ggrid(int M, int N, int batch) {
    return dim3((N + 127) / 128, (M + 127) / 128, batch);
}

extern "C" void kernel_launch(void* const* d_in, const int* in_sizes, int n_in,
                              void* d_out, int out_size)
{
    const float* x      = (const float*)d_in[0];
    const int*   ei     = (const int*)  d_in[1];
    const int*   et     = (const int*)  d_in[3];
    const float* basis  = (const float*)d_in[8];
    const float* comp   = (const float*)d_in[9];
    const float* root1  = (const float*)d_in[10];
    const float* bias1  = (const float*)d_in[11];
    const float* w_rel  = (const float*)d_in[12];
    const float* b_rel  = (const float*)d_in[13];
    const float* w_root = (const float*)d_in[14];
    const float* w_att  = (const float*)d_in[15];
    const float* b_att  = (const float*)d_in[16];
    const float* w_lin  = (const float*)d_in[17];
    const float* b_lin  = (const float*)d_in[18];
    const float* w_fc   = (const float*)d_in[19];
    const float* b_fc   = (const float*)d_in[20];
    float* out = (float*)d_out;

    float *pW, *pxw, *pout1, *pagg2, *pemo, *pX, *pscores, *patt, *phid;
    int* pcnt;
    cudaGetSymbolAddress((void**)&pW,      g_W);
    cudaGetSymbolAddress((void**)&pxw,     g_xw);
    cudaGetSymbolAddress((void**)&pcnt,    g_cnt);
    cudaGetSymbolAddress((void**)&pout1,   g_out1);
    cudaGetSymbolAddress((void**)&pagg2,   g_agg2);
    cudaGetSymbolAddress((void**)&pemo,    g_emo);
    cudaGetSymbolAddress((void**)&pX,      g_X);
    cudaGetSymbolAddress((void**)&pscores, g_scores);
    cudaGetSymbolAddress((void**)&patt,    g_att);
    cudaGetSymbolAddress((void**)&phid,    g_hidden);

    // 1) zero counters & agg2
    zero_f_k<<<(NN_ * RR_ + 255) / 256, 256>>>((float*)pcnt, NN_ * RR_);
    zero_f_k<<<(NN_ * HH_ + 255) / 256, 256>>>(pagg2, NN_ * HH_);

    // 2) edge counts per (dst, rel)
    count_k<<<EE_ / 256, 256>>>(ei, et);

    // 3) W = comp x basis  -> Wcat[F, R*H]
    computeW_k<<<(FF_ * RH_ + 255) / 256, 256>>>(basis, comp);

    // 4) xw = x @ Wcat   [N, RH]
    gemm_k<0, 0, 0, 0><<<ggrid(NN_, RH_, 1), 256>>>(
        x, pW, pxw, nullptr, NN_, RH_, FF_, FF_, RH_, RH_, 0, 0, 0);

    // 5) out1 = x @ root1 + bias1
    gemm_k<0, 0, 0, 1><<<ggrid(NN_, HH_, 1), 256>>>(
        x, root1, pout1, bias1, NN_, HH_, FF_, FF_, HH_, HH_, 0, 0, 0);

    // 6) out1 += scatter(mean per (dst,rel) of xw[src,etype])
    scatter_msg_k<<<EE_ / 8, 256>>>(ei, et);

    // 7) agg2 = scatter_sum(out1[src] -> dst)
    scatter_agg2_k<<<EE_ / 8, 256>>>(ei);

    // 8) emotions = [x | agg2@w_rel + b_rel + out1@w_root]
    copyx_k<<<(NN_ * FF_ / 4 + 255) / 256, 256>>>(x);
    gemm_k<0, 0, 0, 1><<<ggrid(NN_, HH_, 1), 256>>>(
        pagg2, w_rel, pemo + FF_, b_rel, NN_, HH_, HH_, HH_, HH_, DD_, 0, 0, 0);
    gemm_k<0, 0, 1, 0><<<ggrid(NN_, HH_, 1), 256>>>(
        pout1, w_root, pemo + FF_, nullptr, NN_, HH_, HH_, HH_, HH_, DD_, 0, 0, 0);

    // 9) X = emotions @ w_att + b_att
    gemm_k<0, 0, 0, 1><<<ggrid(NN_, DD_, 1), 256>>>(
        pemo, w_att, pX, b_att, NN_, DD_, DD_, DD_, DD_, DD_, 0, 0, 0);

    // 10) scores[b] = tanh(X_b @ M_b^T)   (batched NT, epilogue tanh)
    gemm_k<1, 2, 0, 0><<<ggrid(LL_, LL_, BB_), 256>>>(
        pX, pemo, pscores, nullptr, LL_, LL_, DD_, DD_, DD_, LL_,
        (long long)LL_ * DD_, (long long)LL_ * DD_, (long long)LL_ * LL_);

    // 11) row softmax over s
    softmax_k<<<BB_ * LL_, LL_>>>();

    // 12) att[b] = a_b @ M_b   (batched NN)
    gemm_k<0, 0, 0, 0><<<ggrid(LL_, DD_, BB_), 256>>>(
        pscores, pemo, patt, nullptr, LL_, DD_, LL_, LL_, DD_, DD_,
        (long long)LL_ * LL_, (long long)LL_ * DD_, (long long)LL_ * DD_);

    // 13) hidden = relu(att @ w_lin + b_lin)
    gemm_k<0, 1, 0, 1><<<ggrid(NN_, HH_, 1), 256>>>(
        patt, w_lin, phid, b_lin, NN_, HH_, DD_, DD_, HH_, HH_, 0, 0, 0);

    // 14) logits = hidden @ w_fc + b_fc
    logits_k<<<NN_ / 8, 256>>>(w_fc, b_fc);

    // 15) log_softmax over batch axis, write [L,B,C]
    logsoftmax_k<<<(LL_ * CC_ + 255) / 256, 256>>>(out);
}

// round 7
// speedup vs baseline: 1.9969x; 1.9965x over previous
#include <cuda_runtime.h>
#include <cuda_bf16.h>
#include <stdint.h>
#include <math.h>

#define NN_ 8192
#define FF_ 512
#define HH_ 256
#define RR_ 16
#define BB_ 32
#define LL_ 256
#define CC_ 7
#define EE_ 262144
#define NBASE_ 30
#define DD_ 768
#define RH_ 4096

typedef __nv_bfloat16 bf16;

// ---------------- scratch ----------------
__device__ __align__(16) float g_xw[(size_t)NN_ * RH_];
__device__ int                 g_cnt[NN_ * RR_];
__device__ __align__(16) float g_cat[NN_ * FF_];      // [:,0:256]=agg2 [:,256:512]=out1
__device__ __align__(16) float g_emo[NN_ * DD_];
__device__ __align__(16) float g_scores[BB_ * LL_ * LL_];
__device__ __align__(16) float g_hidden[NN_ * HH_];
__device__ __align__(16) float g_logits[NN_ * CC_];

__device__ __align__(16) bf16 g_xh[NN_*FF_],   g_xl[NN_*FF_];
__device__ __align__(16) bf16 g_wth[RH_*FF_],  g_wtl[RH_*FF_];
__device__ __align__(16) bf16 g_r1th[HH_*FF_], g_r1tl[HH_*FF_];
__device__ __align__(16) bf16 g_w2th[HH_*FF_], g_w2tl[HH_*FF_];
__device__ __align__(16) bf16 g_wath[DD_*DD_], g_watl[DD_*DD_];
__device__ __align__(16) bf16 g_wlth[HH_*DD_], g_wltl[HH_*DD_];
__device__ __align__(16) bf16 g_cath[NN_*FF_], g_catl[NN_*FF_];
__device__ __align__(16) bf16 g_emoh[NN_*DD_], g_emol[NN_*DD_];
__device__ __align__(16) bf16 g_Xh[NN_*DD_],   g_Xl[NN_*DD_];
__device__ __align__(16) bf16 g_ah[BB_*LL_*LL_], g_al[BB_*LL_*LL_];
__device__ __align__(16) bf16 g_eTh[BB_*DD_*LL_], g_eTl[BB_*DD_*LL_];
__device__ __align__(16) bf16 g_atth[NN_*DD_], g_attl[NN_*DD_];

// ---------------- helpers (baseline ISA only: sm_80-level) ----------------
__device__ __forceinline__ uint32_t smem_u32(const void* p) {
    uint32_t a;
    asm("{ .reg .u64 t; cvta.to.shared.u64 t, %1; cvt.u32.u64 %0, t; }" : "=r"(a) : "l"(p));
    return a;
}
__device__ __forceinline__ void cpasync16(uint32_t dst, const void* src) {
    asm volatile("cp.async.cg.shared.global [%0], [%1], 16;" :: "r"(dst), "l"(src));
}
__device__ __forceinline__ void ldsm4(uint32_t* r, uint32_t addr) {
    asm volatile("ldmatrix.sync.aligned.m8n8.x4.shared.b16 {%0,%1,%2,%3}, [%4];"
        : "=r"(r[0]), "=r"(r[1]), "=r"(r[2]), "=r"(r[3]) : "r"(addr));
}
__device__ __forceinline__ void mma16816(float* c, const uint32_t* a, const uint32_t* b) {
    asm volatile("mma.sync.aligned.m16n8k16.row.col.f32.bf16.bf16.f32 "
        "{%0,%1,%2,%3},{%4,%5,%6,%7},{%8,%9},{%0,%1,%2,%3};"
        : "+f"(c[0]), "+f"(c[1]), "+f"(c[2]), "+f"(c[3])
        : "r"(a[0]), "r"(a[1]), "r"(a[2]), "r"(a[3]), "r"(b[0]), "r"(b[1]));
}

// ---------------- HMMA GEMM: C[128x128/CTA] = (Ah+Al) @ (Bh+Bl)^T ----------------
// A [M,K] row-major bf16 split, B [N,K] row-major bf16 split. K%32==0, M,N%128==0.
#define TSTRIDE 80
#define TILE_B  10240
#define STAGE_B 40960
#define SMEM_BYTES (2 * STAGE_B)

template <int EPI, int HASB, int OSPL>
__global__ void __launch_bounds__(256, 1) mmagemm_k(
    const bf16* __restrict__ Ah, const bf16* __restrict__ Al,
    const bf16* __restrict__ Bh, const bf16* __restrict__ Bl,
    float* __restrict__ C, bf16* __restrict__ Oh, bf16* __restrict__ Ol,
    const float* __restrict__ bias,
    int K, int ldc, long long sA, long long sB, long long sC)
{
    extern __shared__ __align__(16) char smem[];
    const int tid = threadIdx.x, lane = tid & 31, wid = tid >> 5;
    const int wm = (wid >> 2) * 64, wn = (wid & 3) * 32;
    const int bm = blockIdx.y << 7, bn = blockIdx.x << 7;
    Ah += blockIdx.z * sA;  Al += blockIdx.z * sA;
    Bh += blockIdx.z * sB;  Bl += blockIdx.z * sB;
    const uint32_t sbase = smem_u32(smem);
    const size_t rsk = (size_t)K * 2;

    float acc[4][4][4];
#pragma unroll
    for (int i = 0; i < 4; i++)
#pragma unroll
        for (int j = 0; j < 4; j++)
#pragma unroll
            for (int r = 0; r < 4; r++) acc[i][j][r] = 0.f;

    const char* pA0 = (const char*)Ah + (size_t)bm * rsk;
    const char* pA1 = (const char*)Al + (size_t)bm * rsk;
    const char* pB0 = (const char*)Bh + (size_t)bn * rsk;
    const char* pB1 = (const char*)Bl + (size_t)bn * rsk;

    auto issue = [&](int stage, int k0) {
        uint32_t d0 = sbase + stage * STAGE_B;
#pragma unroll
        for (int i = 0; i < 2; i++) {
            int task = tid + i * 256;
            int row = task >> 2, ch = task & 3;
            uint32_t doff = row * TSTRIDE + ch * 16;
            size_t goff = (size_t)row * rsk + (size_t)k0 * 2 + ch * 16;
            cpasync16(d0 + doff,              pA0 + goff);
            cpasync16(d0 + TILE_B + doff,     pA1 + goff);
            cpasync16(d0 + 2 * TILE_B + doff, pB0 + goff);
            cpasync16(d0 + 3 * TILE_B + doff, pB1 + goff);
        }
        asm volatile("cp.async.commit_group;" ::: "memory");
    };

    const int NK = K >> 5;
    issue(0, 0);
#pragma unroll 1
    for (int k = 0; k < NK; k++) {
        const int st = k & 1;
        if (k + 1 < NK) {
            issue(st ^ 1, (k + 1) << 5);
            asm volatile("cp.async.wait_group 1;" ::: "memory");
        } else {
            asm volatile("cp.async.wait_group 0;" ::: "memory");
        }
        __syncthreads();
        const uint32_t aB = sbase + st * STAGE_B;
        const int idx8 = lane & 7, q = lane >> 3;
#pragma unroll
        for (int ks = 0; ks < 2; ks++) {
            uint32_t arh[4][4], arl[4][4];
#pragma unroll
            for (int mf = 0; mf < 4; mf++) {
                uint32_t byte = (uint32_t)(wm + mf * 16 + (q & 1) * 8 + idx8) * TSTRIDE
                              + ks * 32 + (q >> 1) * 16;
                ldsm4(arh[mf], aB + byte);
                ldsm4(arl[mf], aB + TILE_B + byte);
            }
            uint32_t brh[4][2], brl[4][2];
#pragma unroll
            for (int nf2 = 0; nf2 < 2; nf2++) {
                uint32_t byte = (uint32_t)(wn + nf2 * 16 + (q >> 1) * 8 + idx8) * TSTRIDE
                              + ks * 32 + (q & 1) * 16;
                uint32_t r[4];
                ldsm4(r, aB + 2 * TILE_B + byte);
                brh[nf2 * 2][0] = r[0]; brh[nf2 * 2][1] = r[1];
                brh[nf2 * 2 + 1][0] = r[2]; brh[nf2 * 2 + 1][1] = r[3];
                ldsm4(r, aB + 3 * TILE_B + byte);
                brl[nf2 * 2][0] = r[0]; brl[nf2 * 2][1] = r[1];
                brl[nf2 * 2 + 1][0] = r[2]; brl[nf2 * 2 + 1][1] = r[3];
            }
#pragma unroll
            for (int mf = 0; mf < 4; mf++)
#pragma unroll
                for (int nf = 0; nf < 4; nf++) {
                    mma16816(acc[mf][nf], arh[mf], brh[nf]);
                    mma16816(acc[mf][nf], arh[mf], brl[nf]);
                    mma16816(acc[mf][nf], arl[mf], brh[nf]);
                }
        }
        __syncthreads();
    }

    // epilogue: direct stores (sector-complete float2 / bf16x2)
#pragma unroll
    for (int mf = 0; mf < 4; mf++) {
#pragma unroll
        for (int rh = 0; rh < 2; rh++) {
            int row = bm + wm + mf * 16 + (lane >> 2) + rh * 8;
#pragma unroll
            for (int nf = 0; nf < 4; nf++) {
                int col = bn + wn + nf * 8 + (lane & 3) * 2;
                float v0 = acc[mf][nf][rh * 2], v1 = acc[mf][nf][rh * 2 + 1];
                if (HASB) { v0 += bias[col]; v1 += bias[col + 1]; }
                if (EPI == 1) { v0 = fmaxf(v0, 0.f); v1 = fmaxf(v1, 0.f); }
                if (EPI == 2) { v0 = tanhf(v0); v1 = tanhf(v1); }
                long long idx = (long long)row * ldc + col + blockIdx.z * sC;
                if (OSPL) {
                    bf16 h0 = __float2bfloat16(v0), h1 = __float2bfloat16(v1);
                    __nv_bfloat162 hp, lp;
                    hp.x = h0; hp.y = h1;
                    lp.x = __float2bfloat16(v0 - __bfloat162float(h0));
                    lp.y = __float2bfloat16(v1 - __bfloat162float(h1));
                    *(__nv_bfloat162*)&Oh[idx] = hp;
                    *(__nv_bfloat162*)&Ol[idx] = lp;
                } else {
                    *(float2*)&C[idx] = make_float2(v0, v1);
                }
            }
        }
    }
}

// ---------------- prep / small kernels ----------------
__global__ void zeroagg_k() {
    int i = blockIdx.x * 256 + threadIdx.x;
    if (i < NN_ * HH_) g_cat[(size_t)(i >> 8) * FF_ + (i & 255)] = 0.f;
}
__global__ void zcnt_k() {
    int i = blockIdx.x * 256 + threadIdx.x;
    if (i < NN_ * RR_) g_cnt[i] = 0;
}
__global__ void count_k(const int* __restrict__ ei, const int* __restrict__ et) {
    int e = blockIdx.x * 256 + threadIdx.x;
    if (e < EE_) atomicAdd(&g_cnt[ei[EE_ + e] * RR_ + et[e]], 1);
}
__global__ void computeWt_k(const float* __restrict__ basis, const float* __restrict__ comp) {
    int i = blockIdx.x * 256 + threadIdx.x;
    if (i >= FF_ * RH_) return;
    int h = i & 255, r = (i >> 8) & 15, f = i >> 12;
    float s = 0.f;
#pragma unroll
    for (int b = 0; b < NBASE_; b++)
        s = fmaf(comp[r * NBASE_ + b], basis[((size_t)b * FF_ + f) * HH_ + h], s);
    size_t o = (size_t)(r * 256 + h) * FF_ + f;
    bf16 hh = __float2bfloat16(s);
    g_wth[o] = hh;
    g_wtl[o] = __float2bfloat16(s - __bfloat162float(hh));
}
__global__ void split_k(const float* __restrict__ in, bf16* __restrict__ oh, bf16* __restrict__ ol, int n) {
    int i = blockIdx.x * 256 + threadIdx.x;
    if (i >= n) return;
    float v = in[i];
    bf16 h = __float2bfloat16(v);
    oh[i] = h;
    ol[i] = __float2bfloat16(v - __bfloat162float(h));
}
__global__ void tsplit_k(const float* __restrict__ in, bf16* __restrict__ oh, bf16* __restrict__ ol,
                         int ldi, int ldo, long long sIn, long long sOut) {
    __shared__ float t[32][33];
    in += blockIdx.z * sIn; oh += blockIdx.z * sOut; ol += blockIdx.z * sOut;
    int bx = blockIdx.x * 32, by = blockIdx.y * 32;
    int tx = threadIdx.x, ty = threadIdx.y;
#pragma unroll
    for (int j = 0; j < 4; ++j)
        t[ty + j * 8][tx] = in[(size_t)(by + ty + j * 8) * ldi + bx + tx];
    __syncthreads();
#pragma unroll
    for (int j = 0; j < 4; ++j) {
        float v = t[tx][ty + j * 8];
        size_t o = (size_t)(bx + ty + j * 8) * ldo + by + tx;
        bf16 h = __float2bfloat16(v);
        oh[o] = h;
        ol[o] = __float2bfloat16(v - __bfloat162float(h));
    }
}
__global__ void xprep_k(const float* __restrict__ x) {
    int i = blockIdx.x * 256 + threadIdx.x;
    if (i >= NN_ * FF_) return;
    float v = x[i];
    bf16 h = __float2bfloat16(v);
    g_xh[i] = h;
    g_xl[i] = __float2bfloat16(v - __bfloat162float(h));
    g_emo[(size_t)(i >> 9) * DD_ + (i & 511)] = v;
}
__global__ void scatter_msg_k(const int* __restrict__ ei, const int* __restrict__ et) {
    int e = blockIdx.x * 8 + (threadIdx.x >> 5);
    int lane = threadIdx.x & 31;
    if (e >= EE_) return;
    int s = ei[e], d = ei[EE_ + e], r = et[e];
    float inv = 1.0f / (float)max(g_cnt[d * RR_ + r], 1);
    const float4* p = (const float4*)(g_xw + (size_t)s * RH_ + r * HH_);
    float* o = g_cat + (size_t)d * FF_ + HH_;
#pragma unroll
    for (int i = 0; i < 2; ++i) {
        float4 v = p[lane + i * 32];
        int h = (lane + i * 32) * 4;
        atomicAdd(o + h + 0, v.x * inv);
        atomicAdd(o + h + 1, v.y * inv);
        atomicAdd(o + h + 2, v.z * inv);
        atomicAdd(o + h + 3, v.w * inv);
    }
}
__global__ void scatter_agg2_k(const int* __restrict__ ei) {
    int e = blockIdx.x * 8 + (threadIdx.x >> 5);
    int lane = threadIdx.x & 31;
    if (e >= EE_) return;
    int s = ei[e], d = ei[EE_ + e];
    const float4* p = (const float4*)(g_cat + (size_t)s * FF_ + HH_);
    float* o = g_cat + (size_t)d * FF_;
#pragma unroll
    for (int i = 0; i < 2; ++i) {
        float4 v = p[lane + i * 32];
        int h = (lane + i * 32) * 4;
        atomicAdd(o + h + 0, v.x);
        atomicAdd(o + h + 1, v.y);
        atomicAdd(o + h + 2, v.z);
        atomicAdd(o + h + 3, v.w);
    }
}
__global__ void softmax_k() {
    float* row = g_scores + (size_t)blockIdx.x * LL_;
    int t = threadIdx.x;
    int lane = t & 31, w = t >> 5;
    __shared__ float red[8];
    float v = row[t];
    float m = v;
#pragma unroll
    for (int o = 16; o > 0; o >>= 1) m = fmaxf(m, __shfl_xor_sync(0xffffffffu, m, o));
    if (lane == 0) red[w] = m;
    __syncthreads();
    m = red[0];
#pragma unroll
    for (int i = 1; i < 8; i++) m = fmaxf(m, red[i]);
    float e = expf(v - m);
    float s = e;
#pragma unroll
    for (int o = 16; o > 0; o >>= 1) s += __shfl_xor_sync(0xffffffffu, s, o);
    __syncthreads();
    if (lane == 0) red[w] = s;
    __syncthreads();
    s = 0.f;
#pragma unroll
    for (int i = 0; i < 8; i++) s += red[i];
    row[t] = e / s;
}
__global__ void logits_k(const float* __restrict__ wfc, const float* __restrict__ bfc) {
    __shared__ float sw[HH_ * CC_];
    for (int i = threadIdx.x; i < HH_ * CC_; i += 256) sw[i] = wfc[i];
    __syncthreads();
    int n = blockIdx.x * 8 + (threadIdx.x >> 5);
    int lane = threadIdx.x & 31;
    const float* h = g_hidden + (size_t)n * HH_;
    float a[CC_];
#pragma unroll
    for (int c = 0; c < CC_; c++) a[c] = 0.f;
    for (int k = lane; k < HH_; k += 32) {
        float hv = h[k];
#pragma unroll
        for (int c = 0; c < CC_; c++) a[c] = fmaf(hv, sw[k * CC_ + c], a[c]);
    }
#pragma unroll
    for (int c = 0; c < CC_; c++)
#pragma unroll
        for (int o = 16; o > 0; o >>= 1) a[c] += __shfl_xor_sync(0xffffffffu, a[c], o);
    if (lane == 0)
#pragma unroll
        for (int c = 0; c < CC_; c++) g_logits[(size_t)n * CC_ + c] = a[c] + bfc[c];
}
__global__ void logsoftmax_k(float* __restrict__ out) {
    int u = blockIdx.x * 256 + threadIdx.x;
    if (u >= LL_ * CC_) return;
    int t = u / CC_, c = u % CC_;
    float vals[BB_];
    float m = -1e30f;
#pragma unroll
    for (int b = 0; b < BB_; b++) {
        vals[b] = g_logits[((size_t)(b * LL_ + t)) * CC_ + c];
        m = fmaxf(m, vals[b]);
    }
    float s = 0.f;
#pragma unroll
    for (int b = 0; b < BB_; b++) s += expf(vals[b] - m);
    float lse = m + logf(s);
#pragma unroll
    for (int b = 0; b < BB_; b++) out[((size_t)t * BB_ + b) * CC_ + c] = vals[b] - lse;
}

// ---------------- host ----------------
extern "C" void kernel_launch(void* const* d_in, const int* in_sizes, int n_in,
                              void* d_out, int out_size)
{
    const float* x      = (const float*)d_in[0];
    const int*   ei     = (const int*)  d_in[1];
    const int*   et     = (const int*)  d_in[3];
    const float* basis  = (const float*)d_in[8];
    const float* comp   = (const float*)d_in[9];
    const float* root1  = (const float*)d_in[10];
    const float* bias1  = (const float*)d_in[11];
    const float* w_rel  = (const float*)d_in[12];
    const float* b_rel  = (const float*)d_in[13];
    const float* w_root = (const float*)d_in[14];
    const float* w_att  = (const float*)d_in[15];
    const float* b_att  = (const float*)d_in[16];
    const float* w_lin  = (const float*)d_in[17];
    const float* b_lin  = (const float*)d_in[18];
    const float* w_fc   = (const float*)d_in[19];
    const float* b_fc   = (const float*)d_in[20];
    float* out = (float*)d_out;

    float *pxw, *pcat, *pemo, *pscores, *phid;
    bf16 *pxh, *pxl, *pwth, *pwtl, *pr1h, *pr1l, *pw2h, *pw2l, *pwah, *pwal,
         *pwlh, *pwll, *pch, *pcl, *peh, *pel, *pXh, *pXl, *pah, *pal,
         *peTh, *peTl, *path, *patl;
    cudaGetSymbolAddress((void**)&pxw, g_xw);
    cudaGetSymbolAddress((void**)&pcat, g_cat);
    cudaGetSymbolAddress((void**)&pemo, g_emo);
    cudaGetSymbolAddress((void**)&pscores, g_scores);
    cudaGetSymbolAddress((void**)&phid, g_hidden);
    cudaGetSymbolAddress((void**)&pxh, g_xh);   cudaGetSymbolAddress((void**)&pxl, g_xl);
    cudaGetSymbolAddress((void**)&pwth, g_wth); cudaGetSymbolAddress((void**)&pwtl, g_wtl);
    cudaGetSymbolAddress((void**)&pr1h, g_r1th); cudaGetSymbolAddress((void**)&pr1l, g_r1tl);
    cudaGetSymbolAddress((void**)&pw2h, g_w2th); cudaGetSymbolAddress((void**)&pw2l, g_w2tl);
    cudaGetSymbolAddress((void**)&pwah, g_wath); cudaGetSymbolAddress((void**)&pwal, g_watl);
    cudaGetSymbolAddress((void**)&pwlh, g_wlth); cudaGetSymbolAddress((void**)&pwll, g_wltl);
    cudaGetSymbolAddress((void**)&pch, g_cath);  cudaGetSymbolAddress((void**)&pcl, g_catl);
    cudaGetSymbolAddress((void**)&peh, g_emoh);  cudaGetSymbolAddress((void**)&pel, g_emol);
    cudaGetSymbolAddress((void**)&pXh, g_Xh);    cudaGetSymbolAddress((void**)&pXl, g_Xl);
    cudaGetSymbolAddress((void**)&pah, g_ah);    cudaGetSymbolAddress((void**)&pal, g_al);
    cudaGetSymbolAddress((void**)&peTh, g_eTh);  cudaGetSymbolAddress((void**)&peTl, g_eTl);
    cudaGetSymbolAddress((void**)&path, g_atth); cudaGetSymbolAddress((void**)&patl, g_attl);

    cudaFuncSetAttribute(mmagemm_k<0,0,0>, cudaFuncAttributeMaxDynamicSharedMemorySize, SMEM_BYTES);
    cudaFuncSetAttribute(mmagemm_k<0,1,0>, cudaFuncAttributeMaxDynamicSharedMemorySize, SMEM_BYTES);
    cudaFuncSetAttribute(mmagemm_k<0,1,1>, cudaFuncAttributeMaxDynamicSharedMemorySize, SMEM_BYTES);
    cudaFuncSetAttribute(mmagemm_k<2,0,0>, cudaFuncAttributeMaxDynamicSharedMemorySize, SMEM_BYTES);
    cudaFuncSetAttribute(mmagemm_k<0,0,1>, cudaFuncAttributeMaxDynamicSharedMemorySize, SMEM_BYTES);
    cudaFuncSetAttribute(mmagemm_k<1,1,0>, cudaFuncAttributeMaxDynamicSharedMemorySize, SMEM_BYTES);

    // prep
    zcnt_k<<<(NN_ * RR_ + 255) / 256, 256>>>();
    zeroagg_k<<<(NN_ * HH_ + 255) / 256, 256>>>();
    count_k<<<EE_ / 256, 256>>>(ei, et);
    computeWt_k<<<FF_ * RH_ / 256, 256>>>(basis, comp);
    xprep_k<<<NN_ * FF_ / 256, 256>>>(x);
    tsplit_k<<<dim3(8, 16, 1), dim3(32, 8)>>>(root1, pr1h, pr1l, HH_, FF_, 0, 0);
    tsplit_k<<<dim3(8, 8, 1),  dim3(32, 8)>>>(w_rel,  pw2h, pw2l, HH_, FF_, 0, 0);
    tsplit_k<<<dim3(8, 8, 1),  dim3(32, 8)>>>(w_root, pw2h + HH_, pw2l + HH_, HH_, FF_, 0, 0);
    tsplit_k<<<dim3(24, 24, 1), dim3(32, 8)>>>(w_att, pwah, pwal, DD_, DD_, 0, 0);
    tsplit_k<<<dim3(8, 24, 1),  dim3(32, 8)>>>(w_lin, pwlh, pwll, HH_, DD_, 0, 0);

    // xw = x @ Wcat  [8192,4096]
    mmagemm_k<0,0,0><<<dim3(32, 64, 1), 256, SMEM_BYTES>>>(
        pxh, pxl, pwth, pwtl, pxw, nullptr, nullptr, nullptr, FF_, RH_, 0, 0, 0);
    // out1 = x @ root1 + bias1  -> g_cat[:,256:512]
    mmagemm_k<0,1,0><<<dim3(2, 64, 1), 256, SMEM_BYTES>>>(
        pxh, pxl, pr1h, pr1l, pcat + HH_, nullptr, nullptr, bias1, FF_, FF_, 0, 0, 0);
    // scatters
    scatter_msg_k<<<EE_ / 8, 256>>>(ei, et);
    scatter_agg2_k<<<EE_ / 8, 256>>>(ei);
    // split cat; out2 = [agg2|out1] @ [w_rel;w_root] + b_rel -> g_emo[:,512:768]
    split_k<<<NN_ * FF_ / 256, 256>>>(pcat, pch, pcl, NN_ * FF_);
    mmagemm_k<0,1,0><<<dim3(2, 64, 1), 256, SMEM_BYTES>>>(
        pch, pcl, pw2h, pw2l, pemo + FF_, nullptr, nullptr, b_rel, FF_, DD_, 0, 0, 0);
    // split emo; X = emo @ w_att + b_att (bf16-split out)
    split_k<<<NN_ * DD_ / 256, 256>>>(pemo, peh, pel, NN_ * DD_);
    mmagemm_k<0,1,1><<<dim3(6, 64, 1), 256, SMEM_BYTES>>>(
        peh, pel, pwah, pwal, nullptr, pXh, pXl, b_att, DD_, DD_, 0, 0, 0);
    // scores = tanh(X_b @ emo_b^T)
    mmagemm_k<2,0,0><<<dim3(2, 2, BB_), 256, SMEM_BYTES>>>(
        pXh, pXl, peh, pel, pscores, nullptr, nullptr, nullptr, DD_, LL_,
        (long long)LL_ * DD_, (long long)LL_ * DD_, (long long)LL_ * LL_);
    softmax_k<<<BB_ * LL_, LL_>>>();
    split_k<<<BB_ * LL_ * LL_ / 256, 256>>>(pscores, pah, pal, BB_ * LL_ * LL_);
    // emo^T per batch
    tsplit_k<<<dim3(24, 8, BB_), dim3(32, 8)>>>(pemo, peTh, peTl, DD_, LL_,
        (long long)LL_ * DD_, (long long)DD_ * LL_);
    // att = a_b @ emo_b (bf16-split out)
    mmagemm_k<0,0,1><<<dim3(6, 2, BB_), 256, SMEM_BYTES>>>(
        pah, pal, peTh, peTl, nullptr, path, patl, nullptr, LL_, DD_,
        (long long)LL_ * LL_, (long long)DD_ * LL_, (long long)LL_ * DD_);
    // hidden = relu(att @ w_lin + b_lin)
    mmagemm_k<1,1,0><<<dim3(2, 64, 1), 256, SMEM_BYTES>>>(
        path, patl, pwlh, pwll, phid, nullptr, nullptr, b_lin, DD_, HH_, 0, 0, 0);
    // logits + log_softmax
    logits_k<<<NN_ / 8, 256>>>(w_fc, b_fc);
    logsoftmax_k<<<(LL_ * CC_ + 255) / 256, 256>>>(out);
}